// round 10
// baseline (speedup 1.0000x reference)
#include <cuda_runtime.h>

// Problem constants (fixed by setup_inputs)
#define NB        64
#define SD        52
#define CELLS     (SD * SD)             // 2704
#define CH        255
#define NCELLS    (NB * CELLS)          // 173056
#define NWARPS_T  (NCELLS / 2)          // 86528: one warp = 2 cells
#define EPSF      1e-6f
#define IOU_T     0.7f
#define SCALE_IDX 2

__global__ void zero_out_kernel(float* out) {
    int t = threadIdx.x;
    if (t < 257) out[t] = 0.0f;
}

__device__ __forceinline__ float warp_sum(float v) {
    #pragma unroll
    for (int o = 16; o > 0; o >>= 1) v += __shfl_down_sync(0xffffffffu, v, o);
    return v;
}

__global__ __launch_bounds__(128, 6) void yolo_loss_kernel(
    const float* __restrict__ yhat,
    const float* __restrict__ ytru,
    const float* __restrict__ anchors,
    float* __restrict__ out)
{
    const int wid  = blockIdx.x * 4 + (threadIdx.x >> 5);  // 0..86527
    const int lane = threadIdx.x & 31;
    const int g    = lane >> 4;          // cell within warp (0..1)
    const int sub  = lane & 15;          // lane within 16-lane cell group

    const int cellG = wid * 2 + g;       // global cell index
    const int n     = cellG / CELLS;     // image
    const int ci    = cellG - n * CELLS; // cell within image
    const int gi    = ci / SD;
    const int gj    = ci - gi * SD;

    const size_t base = (size_t)cellG * CH;
    const float* Hb = yhat + base;
    const float* Yb = ytru + base;

    // ---- Batch ALL loads up front: 30 field LDGs + 30 class LDGs,
    // every one independent of the IOU/argmax result (single memory round).

    // Class chunks: channel c = 5 + sub + 16k, k=0..4 covers 5..84 exactly.
    float h0[5], h1[5], h2[5], y0[5], y1[5], y2[5];
    #pragma unroll
    for (int k = 0; k < 5; k++) {
        int c = 5 + sub + 16 * k;
        h0[k] = __ldg(Hb + 0 * 85 + c);
        h1[k] = __ldg(Hb + 1 * 85 + c);
        h2[k] = __ldg(Hb + 2 * 85 + c);
        y0[k] = __ldg(Yb + 0 * 85 + c);
        y1[k] = __ldg(Yb + 1 * 85 + c);
        y2[k] = __ldg(Yb + 2 * 85 + c);
    }

    // Box fields (broadcast within each 16-lane group).
    const float invS = 1.0f / (float)SD;
    const float fj = (float)gj, fi = (float)gi;

    float hcx[3], hcy[3], hw[3], hh[3], hcf[3];
    float ycx[3], ycy[3], yw[3], yh[3], ycf[3];
    #pragma unroll
    for (int b = 0; b < 3; b++) {
        const float* hb = Hb + b * 85;
        const float* yb = Yb + b * 85;
        hcx[b] = (__ldg(hb + 0) + fj) * invS;
        hcy[b] = (__ldg(hb + 1) + fi) * invS;
        hw[b]  =  __ldg(hb + 2);
        hh[b]  =  __ldg(hb + 3);
        hcf[b] =  __ldg(hb + 4);
        ycx[b] = (__ldg(yb + 0) + fj) * invS;
        ycy[b] = (__ldg(yb + 1) + fi) * invS;
        yw[b]  =  __ldg(yb + 2);
        yh[b]  =  __ldg(yb + 3);
        ycf[b] =  __ldg(yb + 4);
    }

    // ---- IOU 3x3 (group-redundant, register-only).
    int   idx_t[3];
    float best_t[3] = {-1.0f, -1.0f, -1.0f};
    float noobj_acc = 0.0f;
    #pragma unroll
    for (int pb = 0; pb < 3; pb++) {
        float px1 = hcx[pb] - 0.5f * hw[pb], px2 = hcx[pb] + 0.5f * hw[pb];
        float py1 = hcy[pb] - 0.5f * hh[pb], py2 = hcy[pb] + 0.5f * hh[pb];
        float pa  = hw[pb] * hh[pb];
        float m = -1.0f;
        #pragma unroll
        for (int tb = 0; tb < 3; tb++) {
            float wi = fmaxf(fminf(px2, ycx[tb] + 0.5f * yw[tb]) -
                             fmaxf(px1, ycx[tb] - 0.5f * yw[tb]), 0.0f);
            float hi = fmaxf(fminf(py2, ycy[tb] + 0.5f * yh[tb]) -
                             fmaxf(py1, ycy[tb] - 0.5f * yh[tb]), 0.0f);
            float inter = wi * hi;
            float uni = pa + yw[tb] * yh[tb] - inter;
            float iou = inter / (uni + EPSF);
            m = fmaxf(m, iou);
            if (iou > best_t[tb]) { best_t[tb] = iou; idx_t[tb] = pb; }
        }
        if (sub == 0 && m < IOU_T) noobj_acc += hcf[pb] * hcf[pb];  // NO_OBJ_V3
    }

    float ho0 = (ycf[0] > 0.0f) ? 1.0f : 0.0f;
    float ho1 = (ycf[1] > 0.0f) ? 1.0f : 0.0f;
    float ho2 = (ycf[2] > 0.0f) ? 1.0f : 0.0f;

    // ---- Scalar losses (one lane per cell group).
    float coord_acc = 0.0f, obj_acc = 0.0f;
    if (sub == 0) {
        const float* anc = anchors + SCALE_IDX * 6;
        #pragma unroll
        for (int tb = 0; tb < 3; tb++) {
            int pb = idx_t[tb];
            float ho = (tb == 0) ? ho0 : (tb == 1) ? ho1 : ho2;
            float aw_p = __ldg(anc + pb * 2), ah_p = __ldg(anc + pb * 2 + 1);
            float aw_t = __ldg(anc + tb * 2), ah_t = __ldg(anc + tb * 2 + 1);
            float dx = (hcx[pb] - ycx[tb]) * (float)SD;
            float dy = (hcy[pb] - ycy[tb]) * (float)SD;
            float dlw = __logf(hw[pb] / aw_p + EPSF) - __logf(yw[tb] / aw_t + EPSF);
            float dlh = __logf(hh[pb] / ah_p + EPSF) - __logf(yh[tb] / ah_t + EPSF);
            float c = dx * dx + dy * dy + dlw * dlw + dlh * dlh;
            coord_acc += c * ho * (2.0f - yw[tb] * yh[tb]);   // SCALE_COORD
            float dc = hcf[pb] - ycf[tb];
            obj_acc += dc * dc * ho;
        }
    }

    // ---- Class loss: resolve argmax with register selects, not addresses.
    const int p0 = idx_t[0], p1 = idx_t[1], p2 = idx_t[2];
    float cls_acc = 0.0f;
    #pragma unroll
    for (int k = 0; k < 5; k++) {
        float s0 = (p0 == 0) ? h0[k] : (p0 == 1) ? h1[k] : h2[k];
        float s1 = (p1 == 0) ? h0[k] : (p1 == 1) ? h1[k] : h2[k];
        float s2 = (p2 == 0) ? h0[k] : (p2 == 1) ? h1[k] : h2[k];
        float d0 = s0 - y0[k];
        float d1 = s1 - y1[k];
        float d2 = s2 - y2[k];
        cls_acc += d0 * d0 * ho0 + d1 * d1 * ho1 + d2 * d2 * ho2;
    }

    // ---- Warp reduction (both cells share image n: CELLS is even) + atomics.
    coord_acc = warp_sum(coord_acc);
    cls_acc   = warp_sum(cls_acc);
    noobj_acc = warp_sum(noobj_acc);
    obj_acc   = warp_sum(obj_acc);

    if (lane == 0) {
        // layout: coord[0:64) class[64:128) noobj[128:192) obj[192:256) prior
        atomicAdd(out + 0 * NB + n, coord_acc);
        atomicAdd(out + 1 * NB + n, cls_acc);
        atomicAdd(out + 2 * NB + n, noobj_acc);
        atomicAdd(out + 3 * NB + n, obj_acc);
    }
}

extern "C" void kernel_launch(void* const* d_in, const int* in_sizes, int n_in,
                              void* d_out, int out_size) {
    const float* yhat    = (const float*)d_in[0];
    const float* y       = (const float*)d_in[1];
    const float* anchors = (const float*)d_in[2];
    float* out = (float*)d_out;

    zero_out_kernel<<<1, 288>>>(out);
    yolo_loss_kernel<<<NWARPS_T / 4, 128>>>(yhat, y, anchors, out);  // 21632 blocks
}